// round 2
// baseline (speedup 1.0000x reference)
#include <cuda_runtime.h>

#define NN 100000
#define EE 1600000
#define NEDGE (EE + NN)
#define HH 128
#define GG 64
#define OUTD 32

// ---------------- scratch (device globals; no allocation allowed) ------------
__device__ int   g_deg[NN];
__device__ float g_dinv[NN];
__device__ int   g_rowoff[NN + 1];
__device__ int   g_cursor[NN];
__device__ int   g_col[NEDGE];
__device__ float g_w[NEDGE];
__device__ float g_bufA[(size_t)NN * HH];
__device__ float g_bufB[(size_t)NN * HH];
__device__ float g_pool[GG * HH];
__device__ int   g_gcnt[GG];
__device__ int   g_goff[GG + 1];
__device__ int   g_part[128];

// ---------------- init: deg=1 (self loop), cursor=0, pool=0, gcnt=0 ---------
__global__ void k_init() {
    int i = blockIdx.x * blockDim.x + threadIdx.x;
    if (i < NN) { g_deg[i] = 1; g_cursor[i] = 0; }
    if (i < GG) g_gcnt[i] = 0;
    if (i < GG * HH) g_pool[i] = 0.0f;
}

// ---------------- degree histogram over dst --------------------------------
__global__ void k_count(const int* __restrict__ ei) {
    int e = blockIdx.x * blockDim.x + threadIdx.x;
    if (e < EE) atomicAdd(&g_deg[ei[EE + e]], 1);
}

__global__ void k_dinv() {
    int i = blockIdx.x * blockDim.x + threadIdx.x;
    if (i < NN) g_dinv[i] = rsqrtf((float)g_deg[i]);
}

// ---------------- 3-kernel exclusive scan of g_deg -> g_rowoff --------------
#define SCAN_CHUNK 1024
#define SCAN_PARTS ((NN + SCAN_CHUNK - 1) / SCAN_CHUNK)   // 98

__global__ void k_scan_part() {
    __shared__ int s[256];
    int base = blockIdx.x * SCAN_CHUNK;
    int t = threadIdx.x;
    int sum = 0;
#pragma unroll
    for (int j = 0; j < 4; j++) {
        int i = base + t + j * 256;
        if (i < NN) sum += g_deg[i];
    }
    s[t] = sum; __syncthreads();
    for (int off = 128; off; off >>= 1) {
        if (t < off) s[t] += s[t + off];
        __syncthreads();
    }
    if (t == 0) g_part[blockIdx.x] = s[0];
}

__global__ void k_scan_mid() {
    int run = 0;
#pragma unroll
    for (int p = 0; p < SCAN_PARTS; p++) {
        int v = g_part[p];
        g_part[p] = run;
        run += v;
    }
    g_rowoff[NN] = run;   // == NEDGE
}

__global__ void k_scan_final() {
    __shared__ int s[SCAN_CHUNK];
    int t = threadIdx.x;
    int i = blockIdx.x * SCAN_CHUNK + t;
    int v = (i < NN) ? g_deg[i] : 0;
    s[t] = v; __syncthreads();
    for (int off = 1; off < SCAN_CHUNK; off <<= 1) {
        int x = (t >= off) ? s[t - off] : 0;
        __syncthreads();
        s[t] += x;
        __syncthreads();
    }
    if (i < NN) g_rowoff[i] = g_part[blockIdx.x] + s[t] - v;   // exclusive
}

// ---------------- CSR fill (edges + self loops) -----------------------------
__global__ void k_fill(const int* __restrict__ ei) {
    int idx = blockIdx.x * blockDim.x + threadIdx.x;
    if (idx >= NEDGE) return;
    int s, d;
    if (idx < EE) { s = ei[idx]; d = ei[EE + idx]; }
    else          { s = d = idx - EE; }
    int pos = g_rowoff[d] + atomicAdd(&g_cursor[d], 1);
    g_col[pos] = s;
    g_w[pos] = g_dinv[s] * g_dinv[d];
}

// ---------------- fp32 GEMM: g_bufA = A @ W  (A = Ain or g_bufB) ------------
// 128x128 tile, 256 threads, 8x8 microtile, K-chunks of 8.
__global__ void __launch_bounds__(256, 2) k_gemm(const float* __restrict__ Ain,
                                                 const float* __restrict__ W) {
    const float* A = Ain ? Ain : g_bufB;
    __shared__ float As[8][128];
    __shared__ float Ws[8][128];
    int t = threadIdx.x;
    int row0 = blockIdx.x * 128;
    int ty = t >> 4, tx = t & 15;

    float acc[8][8];
#pragma unroll
    for (int i = 0; i < 8; i++)
#pragma unroll
        for (int j = 0; j < 8; j++) acc[i][j] = 0.0f;

    for (int k0 = 0; k0 < 128; k0 += 8) {
        {   // load A chunk (transposed to k-major)
            int r = t >> 1;
            int kk = (t & 1) * 4;
            int grow = row0 + r;
            float4 v = (grow < NN) ? *(const float4*)(A + (size_t)grow * 128 + k0 + kk)
                                   : make_float4(0.f, 0.f, 0.f, 0.f);
            As[kk + 0][r] = v.x; As[kk + 1][r] = v.y;
            As[kk + 2][r] = v.z; As[kk + 3][r] = v.w;
        }
        {   // load W chunk
            int idx = t * 4;
            int kk = idx >> 7, c = idx & 127;
            *(float4*)&Ws[kk][c] = *(const float4*)(W + (size_t)(k0 + kk) * 128 + c);
        }
        __syncthreads();
#pragma unroll
        for (int kk = 0; kk < 8; kk++) {
            float a[8], b[8];
            *(float4*)&a[0] = *(float4*)&As[kk][ty * 8];
            *(float4*)&a[4] = *(float4*)&As[kk][ty * 8 + 4];
            *(float4*)&b[0] = *(float4*)&Ws[kk][tx * 8];
            *(float4*)&b[4] = *(float4*)&Ws[kk][tx * 8 + 4];
#pragma unroll
            for (int i = 0; i < 8; i++)
#pragma unroll
                for (int j = 0; j < 8; j++)
                    acc[i][j] = fmaf(a[i], b[j], acc[i][j]);
        }
        __syncthreads();
    }
#pragma unroll
    for (int i = 0; i < 8; i++) {
        int grow = row0 + ty * 8 + i;
        if (grow < NN) {
            float4 v0 = make_float4(acc[i][0], acc[i][1], acc[i][2], acc[i][3]);
            float4 v1 = make_float4(acc[i][4], acc[i][5], acc[i][6], acc[i][7]);
            *(float4*)(g_bufA + (size_t)grow * 128 + tx * 8)     = v0;
            *(float4*)(g_bufA + (size_t)grow * 128 + tx * 8 + 4) = v1;
        }
    }
}

// ---------------- CSR aggregation: g_bufB[d] = sum_e w*g_bufA[col[e]] + b ---
// one warp per destination row; lane owns a float4 (4 of 128 cols).
__global__ void k_agg(const float* __restrict__ bias, int doRelu) {
    int warp = (blockIdx.x * blockDim.x + threadIdx.x) >> 5;
    int lane = threadIdx.x & 31;
    if (warp >= NN) return;
    int beg = g_rowoff[warp];
    int end = g_rowoff[warp + 1];
    const float4* T4 = (const float4*)g_bufA;
    float4 acc = make_float4(0.f, 0.f, 0.f, 0.f);
    int e = beg;
    for (; e + 3 < end; e += 4) {
        int c0 = g_col[e], c1 = g_col[e + 1], c2 = g_col[e + 2], c3 = g_col[e + 3];
        float w0 = g_w[e], w1 = g_w[e + 1], w2 = g_w[e + 2], w3 = g_w[e + 3];
        float4 v0 = __ldg(&T4[(size_t)c0 * 32 + lane]);
        float4 v1 = __ldg(&T4[(size_t)c1 * 32 + lane]);
        float4 v2 = __ldg(&T4[(size_t)c2 * 32 + lane]);
        float4 v3 = __ldg(&T4[(size_t)c3 * 32 + lane]);
        acc.x = fmaf(w0, v0.x, acc.x); acc.y = fmaf(w0, v0.y, acc.y);
        acc.z = fmaf(w0, v0.z, acc.z); acc.w = fmaf(w0, v0.w, acc.w);
        acc.x = fmaf(w1, v1.x, acc.x); acc.y = fmaf(w1, v1.y, acc.y);
        acc.z = fmaf(w1, v1.z, acc.z); acc.w = fmaf(w1, v1.w, acc.w);
        acc.x = fmaf(w2, v2.x, acc.x); acc.y = fmaf(w2, v2.y, acc.y);
        acc.z = fmaf(w2, v2.z, acc.z); acc.w = fmaf(w2, v2.w, acc.w);
        acc.x = fmaf(w3, v3.x, acc.x); acc.y = fmaf(w3, v3.y, acc.y);
        acc.z = fmaf(w3, v3.z, acc.z); acc.w = fmaf(w3, v3.w, acc.w);
    }
    for (; e < end; e++) {
        int c = g_col[e];
        float w = g_w[e];
        float4 v = __ldg(&T4[(size_t)c * 32 + lane]);
        acc.x = fmaf(w, v.x, acc.x); acc.y = fmaf(w, v.y, acc.y);
        acc.z = fmaf(w, v.z, acc.z); acc.w = fmaf(w, v.w, acc.w);
    }
    float4 b = ((const float4*)bias)[lane];
    acc.x += b.x; acc.y += b.y; acc.z += b.z; acc.w += b.w;
    if (doRelu) {
        acc.x = fmaxf(acc.x, 0.f); acc.y = fmaxf(acc.y, 0.f);
        acc.z = fmaxf(acc.z, 0.f); acc.w = fmaxf(acc.w, 0.f);
    }
    ((float4*)g_bufB)[(size_t)warp * 32 + lane] = acc;
}

// ---------------- pooling ----------------------------------------------------
__global__ void k_gcnt(const int* __restrict__ batch) {
    int i = blockIdx.x * blockDim.x + threadIdx.x;
    if (i < NN) atomicAdd(&g_gcnt[batch[i]], 1);
}

__global__ void k_goff() {
    int run = 0;
#pragma unroll
    for (int g = 0; g < GG; g++) {
        g_goff[g] = run;
        run += g_gcnt[g];
    }
    g_goff[GG] = run;
}

// grid 64*8 blocks x 128 threads: block (g, slice) partial-sums h3 rows
__global__ void k_pool() {
    int g = blockIdx.x >> 3;
    int s = blockIdx.x & 7;
    int col = threadIdx.x;
    int start = g_goff[g];
    int cnt = g_goff[g + 1] - start;
    int chunk = (cnt + 7) >> 3;
    int lo = start + s * chunk;
    int hi = lo + chunk;
    int ge = start + cnt;
    if (hi > ge) hi = ge;
    float sum = 0.f;
    int i = lo;
    for (; i + 3 < hi; i += 4) {
        sum += g_bufB[(size_t)(i + 0) * 128 + col];
        sum += g_bufB[(size_t)(i + 1) * 128 + col];
        sum += g_bufB[(size_t)(i + 2) * 128 + col];
        sum += g_bufB[(size_t)(i + 3) * 128 + col];
    }
    for (; i < hi; i++) sum += g_bufB[(size_t)i * 128 + col];
    if (lo < hi) atomicAdd(&g_pool[g * 128 + col], sum);
}

// ---------------- MLP head ---------------------------------------------------
__global__ void k_mlp(const float* __restrict__ Wo1, const float* __restrict__ bo1,
                      const float* __restrict__ Wo2, const float* __restrict__ bo2,
                      float* __restrict__ out) {
    __shared__ float ps[128];
    __shared__ float zs[64];
    int g = blockIdx.x;
    int t = threadIdx.x;
    float inv = 1.0f / fmaxf((float)g_gcnt[g], 1.0f);
    ps[t]      = g_pool[g * 128 + t] * inv;
    ps[t + 64] = g_pool[g * 128 + t + 64] * inv;
    __syncthreads();
    float z = bo1[t];
#pragma unroll 8
    for (int k = 0; k < 128; k++) z = fmaf(ps[k], Wo1[k * 64 + t], z);
    zs[t] = fmaxf(z, 0.f);
    __syncthreads();
    if (t < OUTD) {
        float o = bo2[t];
#pragma unroll 8
        for (int j = 0; j < 64; j++) o = fmaf(zs[j], Wo2[j * 32 + t], o);
        out[g * OUTD + t] = o;
    }
}

// ---------------- launch ------------------------------------------------------
extern "C" void kernel_launch(void* const* d_in, const int* in_sizes, int n_in,
                              void* d_out, int out_size) {
    const float* x    = (const float*)d_in[0];
    const int*   ei   = (const int*)d_in[1];
    const int*   batch= (const int*)d_in[2];
    const float* W1   = (const float*)d_in[3];
    const float* b1   = (const float*)d_in[4];
    const float* W2   = (const float*)d_in[5];
    const float* b2   = (const float*)d_in[6];
    const float* W3   = (const float*)d_in[7];
    const float* b3   = (const float*)d_in[8];
    const float* Wo1  = (const float*)d_in[9];
    const float* bo1  = (const float*)d_in[10];
    const float* Wo2  = (const float*)d_in[11];
    const float* bo2  = (const float*)d_in[12];
    float* out = (float*)d_out;

    // graph preprocessing (CSR by dst, degrees, norms)
    k_init<<<(NN + 255) / 256, 256>>>();
    k_count<<<(EE + 255) / 256, 256>>>(ei);
    k_dinv<<<(NN + 255) / 256, 256>>>();
    k_scan_part<<<SCAN_PARTS, 256>>>();
    k_scan_mid<<<1, 1>>>();
    k_scan_final<<<SCAN_PARTS, SCAN_CHUNK>>>();
    k_fill<<<(NEDGE + 255) / 256, 256>>>(ei);

    const int GEMM_BLOCKS = (NN + 127) / 128;
    const int AGG_BLOCKS  = (NN + 7) / 8;

    // layer 1
    k_gemm<<<GEMM_BLOCKS, 256>>>(x, W1);
    k_agg<<<AGG_BLOCKS, 256>>>(b1, 1);
    // layer 2
    k_gemm<<<GEMM_BLOCKS, 256>>>(nullptr, W2);
    k_agg<<<AGG_BLOCKS, 256>>>(b2, 1);
    // layer 3
    k_gemm<<<GEMM_BLOCKS, 256>>>(nullptr, W3);
    k_agg<<<AGG_BLOCKS, 256>>>(b3, 0);

    // pooling + head
    k_gcnt<<<(NN + 255) / 256, 256>>>(batch);
    k_goff<<<1, 1>>>();
    k_pool<<<GG * 8, 128>>>();
    k_mlp<<<GG, 64>>>(Wo1, bo1, Wo2, bo2, out);
}

// round 4
// speedup vs baseline: 1.0789x; 1.0789x over previous
#include <cuda_runtime.h>
#include <cuda_fp16.h>
#include <cstdint>

#define NN 100000
#define EE 1600000
#define NEDGE (EE + NN)
#define HH 128
#define GG 64
#define OUTD 32

// ---------------- scratch (device globals; no allocation allowed) ------------
__device__ int    g_deg[NN];
__device__ float  g_dinv[NN];
__device__ int    g_rowoff[NN + 1];
__device__ int    g_cursor[NN];
__device__ int2   g_cw[NEDGE];                    // packed (col, w bits)
__device__ float  g_bufB[(size_t)NN * HH];        // fp32 agg output / GEMM input
__device__ __half g_half[(size_t)NN * HH];        // fp16 GEMM output for gather
__device__ float  g_pool[GG * HH];
__device__ int    g_gcnt[GG];
__device__ int    g_goff[GG + 1];
__device__ int    g_part[128];

// ---------------- init: deg=1 (self loop), cursor=0, pool=0, gcnt=0 ---------
__global__ void k_init() {
    int i = blockIdx.x * blockDim.x + threadIdx.x;
    if (i < NN) { g_deg[i] = 1; g_cursor[i] = 0; }
    if (i < GG) g_gcnt[i] = 0;
    if (i < GG * HH) g_pool[i] = 0.0f;
}

__global__ void k_count(const int* __restrict__ ei) {
    int e = blockIdx.x * blockDim.x + threadIdx.x;
    if (e < EE) atomicAdd(&g_deg[ei[EE + e]], 1);
}

__global__ void k_dinv() {
    int i = blockIdx.x * blockDim.x + threadIdx.x;
    if (i < NN) g_dinv[i] = rsqrtf((float)g_deg[i]);
}

// ---------------- 3-kernel exclusive scan of g_deg -> g_rowoff --------------
#define SCAN_CHUNK 1024
#define SCAN_PARTS ((NN + SCAN_CHUNK - 1) / SCAN_CHUNK)   // 98

__global__ void k_scan_part() {
    __shared__ int s[256];
    int base = blockIdx.x * SCAN_CHUNK;
    int t = threadIdx.x;
    int sum = 0;
#pragma unroll
    for (int j = 0; j < 4; j++) {
        int i = base + t + j * 256;
        if (i < NN) sum += g_deg[i];
    }
    s[t] = sum; __syncthreads();
    for (int off = 128; off; off >>= 1) {
        if (t < off) s[t] += s[t + off];
        __syncthreads();
    }
    if (t == 0) g_part[blockIdx.x] = s[0];
}

__global__ void k_scan_mid() {
    int run = 0;
#pragma unroll
    for (int p = 0; p < SCAN_PARTS; p++) {
        int v = g_part[p];
        g_part[p] = run;
        run += v;
    }
    g_rowoff[NN] = run;   // == NEDGE
}

__global__ void k_scan_final() {
    __shared__ int s[SCAN_CHUNK];
    int t = threadIdx.x;
    int i = blockIdx.x * SCAN_CHUNK + t;
    int v = (i < NN) ? g_deg[i] : 0;
    s[t] = v; __syncthreads();
    for (int off = 1; off < SCAN_CHUNK; off <<= 1) {
        int x = (t >= off) ? s[t - off] : 0;
        __syncthreads();
        s[t] += x;
        __syncthreads();
    }
    if (i < NN) g_rowoff[i] = g_part[blockIdx.x] + s[t] - v;   // exclusive
}

// ---------------- CSR fill (edges + self loops), packed records --------------
__global__ void k_fill(const int* __restrict__ ei) {
    int idx = blockIdx.x * blockDim.x + threadIdx.x;
    if (idx >= NEDGE) return;
    int s, d;
    if (idx < EE) { s = ei[idx]; d = ei[EE + idx]; }
    else          { s = d = idx - EE; }
    int pos = g_rowoff[d] + atomicAdd(&g_cursor[d], 1);
    float w = g_dinv[s] * g_dinv[d];
    g_cw[pos] = make_int2(s, __float_as_int(w));
}

// ---------------- fp32 GEMM: g_half = fp16(A @ W) ----------------------------
// 128x128 tile, 256 threads, 8x8 microtile, K-chunks of 8.
__global__ void __launch_bounds__(256, 2) k_gemm(const float* __restrict__ Ain,
                                                 const float* __restrict__ W) {
    const float* A = Ain ? Ain : g_bufB;
    __shared__ float As[8][128];
    __shared__ float Ws[8][128];
    int t = threadIdx.x;
    int row0 = blockIdx.x * 128;
    int ty = t >> 4, tx = t & 15;

    float acc[8][8];
#pragma unroll
    for (int i = 0; i < 8; i++)
#pragma unroll
        for (int j = 0; j < 8; j++) acc[i][j] = 0.0f;

    for (int k0 = 0; k0 < 128; k0 += 8) {
        {   // load A chunk (transposed to k-major)
            int r = t >> 1;
            int kk = (t & 1) * 4;
            int grow = row0 + r;
            float4 v = (grow < NN) ? *(const float4*)(A + (size_t)grow * 128 + k0 + kk)
                                   : make_float4(0.f, 0.f, 0.f, 0.f);
            As[kk + 0][r] = v.x; As[kk + 1][r] = v.y;
            As[kk + 2][r] = v.z; As[kk + 3][r] = v.w;
        }
        {   // load W chunk
            int idx = t * 4;
            int kk = idx >> 7, c = idx & 127;
            *(float4*)&Ws[kk][c] = *(const float4*)(W + (size_t)(k0 + kk) * 128 + c);
        }
        __syncthreads();
#pragma unroll
        for (int kk = 0; kk < 8; kk++) {
            float a[8], b[8];
            *(float4*)&a[0] = *(float4*)&As[kk][ty * 8];
            *(float4*)&a[4] = *(float4*)&As[kk][ty * 8 + 4];
            *(float4*)&b[0] = *(float4*)&Ws[kk][tx * 8];
            *(float4*)&b[4] = *(float4*)&Ws[kk][tx * 8 + 4];
#pragma unroll
            for (int i = 0; i < 8; i++)
#pragma unroll
                for (int j = 0; j < 8; j++)
                    acc[i][j] = fmaf(a[i], b[j], acc[i][j]);
        }
        __syncthreads();
    }
    // epilogue: fp16 output (halves store + downstream gather traffic)
#pragma unroll
    for (int i = 0; i < 8; i++) {
        int grow = row0 + ty * 8 + i;
        if (grow < NN) {
            __half2 h0 = __floats2half2_rn(acc[i][0], acc[i][1]);
            __half2 h1 = __floats2half2_rn(acc[i][2], acc[i][3]);
            __half2 h2 = __floats2half2_rn(acc[i][4], acc[i][5]);
            __half2 h3 = __floats2half2_rn(acc[i][6], acc[i][7]);
            uint4 v;
            v.x = *(unsigned*)&h0; v.y = *(unsigned*)&h1;
            v.z = *(unsigned*)&h2; v.w = *(unsigned*)&h3;
            *(uint4*)((unsigned short*)g_half + (size_t)grow * 128 + tx * 8) = v;
        }
    }
}

// ---------------- CSR aggregation from fp16 features --------------------------
// one warp per destination row; lane owns 4 cols (uint2 = 4 halves).
__global__ void k_agg_h(const float* __restrict__ bias, int doRelu) {
    int warp = (blockIdx.x * blockDim.x + threadIdx.x) >> 5;
    int lane = threadIdx.x & 31;
    if (warp >= NN) return;
    int beg = g_rowoff[warp];
    int end = g_rowoff[warp + 1];
    const uint2* T = (const uint2*)g_half;   // row = 32 x uint2
    float4 acc0 = make_float4(0.f, 0.f, 0.f, 0.f);
    float4 acc1 = make_float4(0.f, 0.f, 0.f, 0.f);
    int e = beg;
    for (; e + 3 < end; e += 4) {
        int2 cw0 = g_cw[e],     cw1 = g_cw[e + 1];
        int2 cw2 = g_cw[e + 2], cw3 = g_cw[e + 3];
        uint2 u0 = __ldg(&T[(size_t)cw0.x * 32 + lane]);
        uint2 u1 = __ldg(&T[(size_t)cw1.x * 32 + lane]);
        uint2 u2 = __ldg(&T[(size_t)cw2.x * 32 + lane]);
        uint2 u3 = __ldg(&T[(size_t)cw3.x * 32 + lane]);
        float w0 = __int_as_float(cw0.y), w1 = __int_as_float(cw1.y);
        float w2 = __int_as_float(cw2.y), w3 = __int_as_float(cw3.y);
        float2 a0 = __half22float2(*(__half2*)&u0.x), b0 = __half22float2(*(__half2*)&u0.y);
        float2 a1 = __half22float2(*(__half2*)&u1.x), b1 = __half22float2(*(__half2*)&u1.y);
        float2 a2 = __half22float2(*(__half2*)&u2.x), b2 = __half22float2(*(__half2*)&u2.y);
        float2 a3 = __half22float2(*(__half2*)&u3.x), b3 = __half22float2(*(__half2*)&u3.y);
        acc0.x = fmaf(w0, a0.x, acc0.x); acc0.y = fmaf(w0, a0.y, acc0.y);
        acc0.z = fmaf(w0, b0.x, acc0.z); acc0.w = fmaf(w0, b0.y, acc0.w);
        acc1.x = fmaf(w1, a1.x, acc1.x); acc1.y = fmaf(w1, a1.y, acc1.y);
        acc1.z = fmaf(w1, b1.x, acc1.z); acc1.w = fmaf(w1, b1.y, acc1.w);
        acc0.x = fmaf(w2, a2.x, acc0.x); acc0.y = fmaf(w2, a2.y, acc0.y);
        acc0.z = fmaf(w2, b2.x, acc0.z); acc0.w = fmaf(w2, b2.y, acc0.w);
        acc1.x = fmaf(w3, a3.x, acc1.x); acc1.y = fmaf(w3, a3.y, acc1.y);
        acc1.z = fmaf(w3, b3.x, acc1.z); acc1.w = fmaf(w3, b3.y, acc1.w);
    }
    for (; e < end; e++) {
        int2 cw = g_cw[e];
        float w = __int_as_float(cw.y);
        uint2 u = __ldg(&T[(size_t)cw.x * 32 + lane]);
        float2 a = __half22float2(*(__half2*)&u.x);
        float2 b = __half22float2(*(__half2*)&u.y);
        acc0.x = fmaf(w, a.x, acc0.x); acc0.y = fmaf(w, a.y, acc0.y);
        acc0.z = fmaf(w, b.x, acc0.z); acc0.w = fmaf(w, b.y, acc0.w);
    }
    float4 b4 = ((const float4*)bias)[lane];
    float4 r;
    r.x = acc0.x + acc1.x + b4.x;
    r.y = acc0.y + acc1.y + b4.y;
    r.z = acc0.z + acc1.z + b4.z;
    r.w = acc0.w + acc1.w + b4.w;
    if (doRelu) {
        r.x = fmaxf(r.x, 0.f); r.y = fmaxf(r.y, 0.f);
        r.z = fmaxf(r.z, 0.f); r.w = fmaxf(r.w, 0.f);
    }
    ((float4*)g_bufB)[(size_t)warp * 32 + lane] = r;
}

// ---------------- pooling ------------------------------------------------------
__global__ void k_gcnt(const int* __restrict__ batch) {
    int i = blockIdx.x * blockDim.x + threadIdx.x;
    if (i < NN) atomicAdd(&g_gcnt[batch[i]], 1);
}

__global__ void k_goff() {
    int run = 0;
#pragma unroll
    for (int g = 0; g < GG; g++) {
        g_goff[g] = run;
        run += g_gcnt[g];
    }
    g_goff[GG] = run;
}

__global__ void k_pool() {
    int g = blockIdx.x >> 3;
    int s = blockIdx.x & 7;
    int col = threadIdx.x;
    int start = g_goff[g];
    int cnt = g_goff[g + 1] - start;
    int chunk = (cnt + 7) >> 3;
    int lo = start + s * chunk;
    int hi = lo + chunk;
    int ge = start + cnt;
    if (hi > ge) hi = ge;
    float sum = 0.f;
    int i = lo;
    for (; i + 3 < hi; i += 4) {
        sum += g_bufB[(size_t)(i + 0) * 128 + col];
        sum += g_bufB[(size_t)(i + 1) * 128 + col];
        sum += g_bufB[(size_t)(i + 2) * 128 + col];
        sum += g_bufB[(size_t)(i + 3) * 128 + col];
    }
    for (; i < hi; i++) sum += g_bufB[(size_t)i * 128 + col];
    if (lo < hi) atomicAdd(&g_pool[g * 128 + col], sum);
}

// ---------------- MLP head ------------------------------------------------------
__global__ void k_mlp(const float* __restrict__ Wo1, const float* __restrict__ bo1,
                      const float* __restrict__ Wo2, const float* __restrict__ bo2,
                      float* __restrict__ out) {
    __shared__ float ps[128];
    __shared__ float zs[64];
    int g = blockIdx.x;
    int t = threadIdx.x;
    float inv = 1.0f / fmaxf((float)g_gcnt[g], 1.0f);
    ps[t]      = g_pool[g * 128 + t] * inv;
    ps[t + 64] = g_pool[g * 128 + t + 64] * inv;
    __syncthreads();
    float z = bo1[t];
#pragma unroll 8
    for (int k = 0; k < 128; k++) z = fmaf(ps[k], Wo1[k * 64 + t], z);
    zs[t] = fmaxf(z, 0.f);
    __syncthreads();
    if (t < OUTD) {
        float o = bo2[t];
#pragma unroll 8
        for (int j = 0; j < 64; j++) o = fmaf(zs[j], Wo2[j * 32 + t], o);
        out[g * OUTD + t] = o;
    }
}

// ---------------- launch ---------------------------------------------------------
extern "C" void kernel_launch(void* const* d_in, const int* in_sizes, int n_in,
                              void* d_out, int out_size) {
    const float* x    = (const float*)d_in[0];
    const int*   ei   = (const int*)d_in[1];
    const int*   batch= (const int*)d_in[2];
    const float* W1   = (const float*)d_in[3];
    const float* b1   = (const float*)d_in[4];
    const float* W2   = (const float*)d_in[5];
    const float* b2   = (const float*)d_in[6];
    const float* W3   = (const float*)d_in[7];
    const float* b3   = (const float*)d_in[8];
    const float* Wo1  = (const float*)d_in[9];
    const float* bo1  = (const float*)d_in[10];
    const float* Wo2  = (const float*)d_in[11];
    const float* bo2  = (const float*)d_in[12];
    float* out = (float*)d_out;

    // graph preprocessing (CSR by dst, degrees, norms)
    k_init<<<(NN + 255) / 256, 256>>>();
    k_count<<<(EE + 255) / 256, 256>>>(ei);
    k_dinv<<<(NN + 255) / 256, 256>>>();
    k_scan_part<<<SCAN_PARTS, 256>>>();
    k_scan_mid<<<1, 1>>>();
    k_scan_final<<<SCAN_PARTS, SCAN_CHUNK>>>();
    k_fill<<<(NEDGE + 255) / 256, 256>>>(ei);
    k_gcnt<<<(NN + 255) / 256, 256>>>(batch);
    k_goff<<<1, 1>>>();

    const int GEMM_BLOCKS = (NN + 127) / 128;
    const int AGG_BLOCKS  = (NN + 7) / 8;

    // layer 1
    k_gemm<<<GEMM_BLOCKS, 256>>>(x, W1);
    k_agg_h<<<AGG_BLOCKS, 256>>>(b1, 1);
    // layer 2
    k_gemm<<<GEMM_BLOCKS, 256>>>(nullptr, W2);
    k_agg_h<<<AGG_BLOCKS, 256>>>(b2, 1);
    // layer 3
    k_gemm<<<GEMM_BLOCKS, 256>>>(nullptr, W3);
    k_agg_h<<<AGG_BLOCKS, 256>>>(b3, 0);

    // pooling + head
    k_pool<<<GG * 8, 128>>>();
    k_mlp<<<GG, 64>>>(Wo1, bo1, Wo2, bo2, out);
}

// round 5
// speedup vs baseline: 1.3651x; 1.2654x over previous
#include <cuda_runtime.h>
#include <cuda_fp16.h>
#include <cuda_bf16.h>
#include <cstdint>

#define NN 100000
#define EE 1600000
#define NEDGE (EE + NN)
#define HH 128
#define GG 64
#define OUTD 32

// ---------------- scratch (device globals; no allocation allowed) ------------
__device__ int    g_deg[NN];
__device__ float  g_dinv[NN];
__device__ int    g_rowoff[NN + 1];
__device__ int    g_cursor[NN];
__device__ int2   g_cw[NEDGE];                    // packed (col, w bits)
__device__ float  g_bufB[(size_t)NN * HH];        // fp32 agg output / GEMM input
__device__ __half g_half[(size_t)NN * HH];        // fp16 GEMM output for gather
__device__ uint4  g_Wh4[3 * 2176];                // W^T bf16 hi, padded [128][136]
__device__ uint4  g_Wl4[3 * 2176];                // W^T bf16 lo
__device__ float  g_pool[GG * HH];
__device__ int    g_gcnt[GG];
__device__ int    g_goff[GG + 1];
__device__ int    g_part[128];

__device__ __forceinline__ unsigned pack_bf2(float x, float y) {
    __nv_bfloat162 h = __floats2bfloat162_rn(x, y);
    return *(unsigned*)&h;
}

// ---------------- init ---------------------------------------------------------
__global__ void k_init() {
    int i = blockIdx.x * blockDim.x + threadIdx.x;
    if (i < NN) { g_deg[i] = 1; g_cursor[i] = 0; }
    if (i < GG) g_gcnt[i] = 0;
    if (i < GG * HH) g_pool[i] = 0.0f;
}

// degree histogram over dst + per-graph node counts (fused)
__global__ void k_count(const int* __restrict__ ei, const int* __restrict__ batch) {
    int e = blockIdx.x * blockDim.x + threadIdx.x;
    if (e < EE) atomicAdd(&g_deg[ei[EE + e]], 1);
    if (e < NN) atomicAdd(&g_gcnt[batch[e]], 1);
}

// ---------------- W -> transposed bf16 hi/lo images [n][k], stride 136 ---------
__global__ void k_prepW(const float* __restrict__ W1, const float* __restrict__ W2,
                        const float* __restrict__ W3) {
    const float* Ws[3] = {W1, W2, W3};
    int l = blockIdx.x;
    const float* W = Ws[l];
    unsigned short* dh = (unsigned short*)(g_Wh4 + l * 2176);
    unsigned short* dl = (unsigned short*)(g_Wl4 + l * 2176);
#pragma unroll
    for (int it = 0; it < 64; it++) {
        int idx = it * 256 + threadIdx.x;      // 16384 = (n, k)
        int n = idx >> 7, k = idx & 127;
        float w = W[k * 128 + n];
        __nv_bfloat16 hi = __float2bfloat16(w);
        float resid = w - __bfloat162float(hi);
        __nv_bfloat16 lo = __float2bfloat16(resid);
        dh[n * 136 + k] = __bfloat16_as_ushort(hi);
        dl[n * 136 + k] = __bfloat16_as_ushort(lo);
    }
}

// ---------------- scans (dinv fused into part; goff fused into mid) ------------
#define SCAN_CHUNK 1024
#define SCAN_PARTS ((NN + SCAN_CHUNK - 1) / SCAN_CHUNK)

__global__ void k_scan_part() {
    __shared__ int s[256];
    int base = blockIdx.x * SCAN_CHUNK;
    int t = threadIdx.x;
    int sum = 0;
#pragma unroll
    for (int j = 0; j < 4; j++) {
        int i = base + t + j * 256;
        if (i < NN) {
            int d = g_deg[i];
            sum += d;
            g_dinv[i] = rsqrtf((float)d);
        }
    }
    s[t] = sum; __syncthreads();
    for (int off = 128; off; off >>= 1) {
        if (t < off) s[t] += s[t + off];
        __syncthreads();
    }
    if (t == 0) g_part[blockIdx.x] = s[0];
}

__global__ void k_scan_mid() {
    int run = 0;
#pragma unroll
    for (int p = 0; p < SCAN_PARTS; p++) {
        int v = g_part[p];
        g_part[p] = run;
        run += v;
    }
    g_rowoff[NN] = run;
    int g = 0;
#pragma unroll
    for (int q = 0; q < GG; q++) {
        g_goff[q] = g;
        g += g_gcnt[q];
    }
    g_goff[GG] = g;
}

__global__ void k_scan_final() {
    __shared__ int s[SCAN_CHUNK];
    int t = threadIdx.x;
    int i = blockIdx.x * SCAN_CHUNK + t;
    int v = (i < NN) ? g_deg[i] : 0;
    s[t] = v; __syncthreads();
    for (int off = 1; off < SCAN_CHUNK; off <<= 1) {
        int x = (t >= off) ? s[t - off] : 0;
        __syncthreads();
        s[t] += x;
        __syncthreads();
    }
    if (i < NN) g_rowoff[i] = g_part[blockIdx.x] + s[t] - v;
}

__global__ void k_fill(const int* __restrict__ ei) {
    int idx = blockIdx.x * blockDim.x + threadIdx.x;
    if (idx >= NEDGE) return;
    int s, d;
    if (idx < EE) { s = ei[idx]; d = ei[EE + idx]; }
    else          { s = d = idx - EE; }
    int pos = g_rowoff[d] + atomicAdd(&g_cursor[d], 1);
    float w = g_dinv[s] * g_dinv[d];
    g_cw[pos] = make_int2(s, __float_as_int(w));
}

// ---------------- tensor-core GEMM (mma.sync bf16x3): g_half = fp16(A @ W) -----
// block = 128x128 tile, 256 threads / 8 warps, warp = 16 rows x 128 cols.
#define SA_HI 0
#define SA_LO 34816
#define SB_HI 69632
#define SB_LO 104448
#define GSM   139264

#define MMA_BF16(C, A0, A1, A2, A3, B0, B1) \
    asm volatile("mma.sync.aligned.m16n8k16.row.col.f32.bf16.bf16.f32 " \
                 "{%0,%1,%2,%3}, {%4,%5,%6,%7}, {%8,%9}, {%0,%1,%2,%3};" \
                 : "+f"((C)[0]), "+f"((C)[1]), "+f"((C)[2]), "+f"((C)[3]) \
                 : "r"(A0), "r"(A1), "r"(A2), "r"(A3), "r"(B0), "r"(B1))

__global__ void __launch_bounds__(256, 1) k_gemm_mma(const float* __restrict__ Ain,
                                                     int layer) {
    extern __shared__ char smem[];
    const float* A = (layer == 0) ? Ain : g_bufB;
    int tid = threadIdx.x;
    int row0 = blockIdx.x << 7;

    // stage A tile: fp32 -> bf16 hi/lo, padded stride 136 halves (68 words)
    {
        uint2* dh = (uint2*)(smem + SA_HI);
        uint2* dl = (uint2*)(smem + SA_LO);
#pragma unroll
        for (int it = 0; it < 16; it++) {
            int idx = it * 256 + tid;         // 4096 float4 chunks
            int row = idx >> 5, c4 = idx & 31;
            int grow = row0 + row;
            float4 v = (grow < NN) ? *(const float4*)(A + (size_t)grow * 128 + c4 * 4)
                                   : make_float4(0.f, 0.f, 0.f, 0.f);
            __nv_bfloat162 h0 = __floats2bfloat162_rn(v.x, v.y);
            __nv_bfloat162 h1 = __floats2bfloat162_rn(v.z, v.w);
            float2 r0 = make_float2(v.x - __bfloat162float(h0.x),
                                    v.y - __bfloat162float(h0.y));
            float2 r1 = make_float2(v.z - __bfloat162float(h1.x),
                                    v.w - __bfloat162float(h1.y));
            uint2 hv, lv;
            hv.x = *(unsigned*)&h0; hv.y = *(unsigned*)&h1;
            lv.x = pack_bf2(r0.x, r0.y); lv.y = pack_bf2(r1.x, r1.y);
            dh[row * 34 + c4] = hv;
            dl[row * 34 + c4] = lv;
        }
    }
    // stage W^T bf16 hi/lo images (pre-split in global)
    {
        const uint4* sh = g_Wh4 + layer * 2176;
        const uint4* sl = g_Wl4 + layer * 2176;
        uint4* dh = (uint4*)(smem + SB_HI);
        uint4* dl = (uint4*)(smem + SB_LO);
#pragma unroll
        for (int it = 0; it < 9; it++) {
            int i = it * 256 + tid;
            if (i < 2176) { dh[i] = __ldg(&sh[i]); dl[i] = __ldg(&sl[i]); }
        }
    }
    __syncthreads();

    const uint32_t* pAhi = (const uint32_t*)(smem + SA_HI);
    const uint32_t* pAlo = (const uint32_t*)(smem + SA_LO);
    const uint32_t* pBhi = (const uint32_t*)(smem + SB_HI);
    const uint32_t* pBlo = (const uint32_t*)(smem + SB_LO);

    int lane = tid & 31, warp = tid >> 5;
    int rq = lane >> 2;        // 0..7
    int q = lane & 3;          // 0..3
    int arow = warp * 16 + rq;

    float c[16][4];
#pragma unroll
    for (int t = 0; t < 16; t++)
#pragma unroll
        for (int j = 0; j < 4; j++) c[t][j] = 0.f;

#pragma unroll
    for (int kk = 0; kk < 8; kk++) {
        int ab = arow * 68 + kk * 8 + q;
        uint32_t ah0 = pAhi[ab],       ah1 = pAhi[ab + 544];
        uint32_t ah2 = pAhi[ab + 4],   ah3 = pAhi[ab + 548];
        uint32_t al0 = pAlo[ab],       al1 = pAlo[ab + 544];
        uint32_t al2 = pAlo[ab + 4],   al3 = pAlo[ab + 548];
#pragma unroll
        for (int t = 0; t < 16; t++) {
            int bb = (t * 8 + rq) * 68 + kk * 8 + q;
            uint32_t bh0 = pBhi[bb], bh1 = pBhi[bb + 4];
            uint32_t bl0 = pBlo[bb], bl1 = pBlo[bb + 4];
            MMA_BF16(c[t], ah0, ah1, ah2, ah3, bh0, bh1);
            MMA_BF16(c[t], al0, al1, al2, al3, bh0, bh1);
            MMA_BF16(c[t], ah0, ah1, ah2, ah3, bl0, bl1);
        }
    }

    // epilogue: fp16 stores straight from fragments
    unsigned short* gh = (unsigned short*)g_half;
    int r1 = row0 + arow, r2 = r1 + 8;
#pragma unroll
    for (int t = 0; t < 16; t++) {
        int col = t * 8 + q * 2;
        if (r1 < NN) {
            __half2 h = __floats2half2_rn(c[t][0], c[t][1]);
            *(unsigned*)(gh + (size_t)r1 * 128 + col) = *(unsigned*)&h;
        }
        if (r2 < NN) {
            __half2 h = __floats2half2_rn(c[t][2], c[t][3]);
            *(unsigned*)(gh + (size_t)r2 * 128 + col) = *(unsigned*)&h;
        }
    }
}

// ---------------- CSR aggregation from fp16 features ----------------------------
__global__ void k_agg_h(const float* __restrict__ bias, int doRelu) {
    int warp = (blockIdx.x * blockDim.x + threadIdx.x) >> 5;
    int lane = threadIdx.x & 31;
    if (warp >= NN) return;
    int beg = g_rowoff[warp];
    int end = g_rowoff[warp + 1];
    const uint2* T = (const uint2*)g_half;
    float4 acc0 = make_float4(0.f, 0.f, 0.f, 0.f);
    float4 acc1 = make_float4(0.f, 0.f, 0.f, 0.f);
    int e = beg;
    for (; e + 3 < end; e += 4) {
        int2 cw0 = g_cw[e],     cw1 = g_cw[e + 1];
        int2 cw2 = g_cw[e + 2], cw3 = g_cw[e + 3];
        uint2 u0 = __ldg(&T[(size_t)cw0.x * 32 + lane]);
        uint2 u1 = __ldg(&T[(size_t)cw1.x * 32 + lane]);
        uint2 u2 = __ldg(&T[(size_t)cw2.x * 32 + lane]);
        uint2 u3 = __ldg(&T[(size_t)cw3.x * 32 + lane]);
        float w0 = __int_as_float(cw0.y), w1 = __int_as_float(cw1.y);
        float w2 = __int_as_float(cw2.y), w3 = __int_as_float(cw3.y);
        float2 a0 = __half22float2(*(__half2*)&u0.x), b0 = __half22float2(*(__half2*)&u0.y);
        float2 a1 = __half22float2(*(__half2*)&u1.x), b1 = __half22float2(*(__half2*)&u1.y);
        float2 a2 = __half22float2(*(__half2*)&u2.x), b2 = __half22float2(*(__half2*)&u2.y);
        float2 a3 = __half22float2(*(__half2*)&u3.x), b3 = __half22float2(*(__half2*)&u3.y);
        acc0.x = fmaf(w0, a0.x, acc0.x); acc0.y = fmaf(w0, a0.y, acc0.y);
        acc0.z = fmaf(w0, b0.x, acc0.z); acc0.w = fmaf(w0, b0.y, acc0.w);
        acc1.x = fmaf(w1, a1.x, acc1.x); acc1.y = fmaf(w1, a1.y, acc1.y);
        acc1.z = fmaf(w1, b1.x, acc1.z); acc1.w = fmaf(w1, b1.y, acc1.w);
        acc0.x = fmaf(w2, a2.x, acc0.x); acc0.y = fmaf(w2, a2.y, acc0.y);
        acc0.z = fmaf(w2, b2.x, acc0.z); acc0.w = fmaf(w2, b2.y, acc0.w);
        acc1.x = fmaf(w3, a3.x, acc1.x); acc1.y = fmaf(w3, a3.y, acc1.y);
        acc1.z = fmaf(w3, b3.x, acc1.z); acc1.w = fmaf(w3, b3.y, acc1.w);
    }
    for (; e < end; e++) {
        int2 cw = g_cw[e];
        float w = __int_as_float(cw.y);
        uint2 u = __ldg(&T[(size_t)cw.x * 32 + lane]);
        float2 a = __half22float2(*(__half2*)&u.x);
        float2 b = __half22float2(*(__half2*)&u.y);
        acc0.x = fmaf(w, a.x, acc0.x); acc0.y = fmaf(w, a.y, acc0.y);
        acc0.z = fmaf(w, b.x, acc0.z); acc0.w = fmaf(w, b.y, acc0.w);
    }
    float4 b4 = ((const float4*)bias)[lane];
    float4 r;
    r.x = acc0.x + acc1.x + b4.x;
    r.y = acc0.y + acc1.y + b4.y;
    r.z = acc0.z + acc1.z + b4.z;
    r.w = acc0.w + acc1.w + b4.w;
    if (doRelu) {
        r.x = fmaxf(r.x, 0.f); r.y = fmaxf(r.y, 0.f);
        r.z = fmaxf(r.z, 0.f); r.w = fmaxf(r.w, 0.f);
    }
    ((float4*)g_bufB)[(size_t)warp * 32 + lane] = r;
}

// ---------------- pooling --------------------------------------------------------
__global__ void k_pool() {
    int g = blockIdx.x >> 3;
    int s = blockIdx.x & 7;
    int col = threadIdx.x;
    int start = g_goff[g];
    int cnt = g_goff[g + 1] - start;
    int chunk = (cnt + 7) >> 3;
    int lo = start + s * chunk;
    int hi = lo + chunk;
    int ge = start + cnt;
    if (hi > ge) hi = ge;
    float sum = 0.f;
    int i = lo;
    for (; i + 3 < hi; i += 4) {
        sum += g_bufB[(size_t)(i + 0) * 128 + col];
        sum += g_bufB[(size_t)(i + 1) * 128 + col];
        sum += g_bufB[(size_t)(i + 2) * 128 + col];
        sum += g_bufB[(size_t)(i + 3) * 128 + col];
    }
    for (; i < hi; i++) sum += g_bufB[(size_t)i * 128 + col];
    if (lo < hi) atomicAdd(&g_pool[g * 128 + col], sum);
}

// ---------------- MLP head --------------------------------------------------------
__global__ void k_mlp(const float* __restrict__ Wo1, const float* __restrict__ bo1,
                      const float* __restrict__ Wo2, const float* __restrict__ bo2,
                      float* __restrict__ out) {
    __shared__ float ps[128];
    __shared__ float zs[64];
    int g = blockIdx.x;
    int t = threadIdx.x;
    float inv = 1.0f / fmaxf((float)g_gcnt[g], 1.0f);
    ps[t]      = g_pool[g * 128 + t] * inv;
    ps[t + 64] = g_pool[g * 128 + t + 64] * inv;
    __syncthreads();
    float z = bo1[t];
#pragma unroll 8
    for (int k = 0; k < 128; k++) z = fmaf(ps[k], Wo1[k * 64 + t], z);
    zs[t] = fmaxf(z, 0.f);
    __syncthreads();
    if (t < OUTD) {
        float o = bo2[t];
#pragma unroll 8
        for (int j = 0; j < 64; j++) o = fmaf(zs[j], Wo2[j * 32 + t], o);
        out[g * OUTD + t] = o;
    }
}

// ---------------- launch ------------------------------------------------------------
extern "C" void kernel_launch(void* const* d_in, const int* in_sizes, int n_in,
                              void* d_out, int out_size) {
    const float* x    = (const float*)d_in[0];
    const int*   ei   = (const int*)d_in[1];
    const int*   batch= (const int*)d_in[2];
    const float* W1   = (const float*)d_in[3];
    const float* b1   = (const float*)d_in[4];
    const float* W2   = (const float*)d_in[5];
    const float* b2   = (const float*)d_in[6];
    const float* W3   = (const float*)d_in[7];
    const float* b3   = (const float*)d_in[8];
    const float* Wo1  = (const float*)d_in[9];
    const float* bo1  = (const float*)d_in[10];
    const float* Wo2  = (const float*)d_in[11];
    const float* bo2  = (const float*)d_in[12];
    float* out = (float*)d_out;

    cudaFuncSetAttribute(k_gemm_mma, cudaFuncAttributeMaxDynamicSharedMemorySize, GSM);

    const int GEMM_BLOCKS = (NN + 127) / 128;
    const int AGG_BLOCKS  = (NN + 7) / 8;

    k_init<<<(NN + 255) / 256, 256>>>();                 // 0
    k_count<<<(EE + 255) / 256, 256>>>(ei, batch);       // 1
    k_prepW<<<3, 256>>>(W1, W2, W3);                     // 2
    k_gemm_mma<<<GEMM_BLOCKS, 256, GSM>>>(x, 0);         // 3  <- ncu slot
    k_scan_part<<<SCAN_PARTS, 256>>>();                  // 4
    k_scan_mid<<<1, 1>>>();                              // 5
    k_scan_final<<<SCAN_PARTS, SCAN_CHUNK>>>();          // 6
    k_fill<<<(NEDGE + 255) / 256, 256>>>(ei);            // 7

    k_agg_h<<<AGG_BLOCKS, 256>>>(b1, 1);                 // 8
    k_gemm_mma<<<GEMM_BLOCKS, 256, GSM>>>(x, 1);         // 9
    k_agg_h<<<AGG_BLOCKS, 256>>>(b2, 1);                 // 10
    k_gemm_mma<<<GEMM_BLOCKS, 256, GSM>>>(x, 2);         // 11
    k_agg_h<<<AGG_BLOCKS, 256>>>(b3, 0);                 // 12

    k_pool<<<GG * 8, 128>>>();                           // 13
    k_mlp<<<GG, 64>>>(Wo1, bo1, Wo2, bo2, out);          // 14
}

// round 6
// speedup vs baseline: 1.3869x; 1.0159x over previous
#include <cuda_runtime.h>
#include <cuda_fp16.h>
#include <cuda_bf16.h>
#include <cstdint>

#define NN 100000
#define EE 1600000
#define NEDGE (EE + NN)
#define HH 128
#define GG 64
#define OUTD 32

// ---------------- scratch (device globals; no allocation allowed) ------------
__device__ int    g_deg[NN];
__device__ float  g_dinv[NN];
__device__ int    g_rowoff[NN + 1];
__device__ int    g_cursor[NN];
__device__ int2   g_cw[NEDGE];                    // packed (col, w bits)
__device__ float  g_bufB[(size_t)NN * HH];        // fp32 agg output / GEMM input
__device__ __half g_half[(size_t)NN * HH];        // fp16 GEMM output for gather
__device__ uint4  g_Wiv[3 * 4352];                // W^T interleaved {hi,lo} words, [128][68] uint2
__device__ float  g_pool[GG * HH];
__device__ int    g_gcnt[GG];
__device__ int    g_goff[GG + 1];
__device__ int    g_part[128];

__device__ __forceinline__ void split_f2(float2 f, uint32_t& hi, uint32_t& lo) {
    __nv_bfloat162 h = __floats2bfloat162_rn(f.x, f.y);
    hi = *(unsigned*)&h;
    float rx = f.x - __bfloat162float(h.x);
    float ry = f.y - __bfloat162float(h.y);
    __nv_bfloat162 l = __floats2bfloat162_rn(rx, ry);
    lo = *(unsigned*)&l;
}

// ---------------- init ---------------------------------------------------------
__global__ void k_init() {
    int i = blockIdx.x * blockDim.x + threadIdx.x;
    if (i < NN) { g_deg[i] = 1; g_cursor[i] = 0; }
    if (i < GG) g_gcnt[i] = 0;
    if (i < GG * HH) g_pool[i] = 0.0f;
}

// degree histogram over dst + per-graph node counts (fused)
__global__ void k_count(const int* __restrict__ ei, const int* __restrict__ batch) {
    int e = blockIdx.x * blockDim.x + threadIdx.x;
    if (e < EE) atomicAdd(&g_deg[ei[EE + e]], 1);
    if (e < NN) atomicAdd(&g_gcnt[batch[e]], 1);
}

// ---------------- W -> transposed interleaved bf16 {hi,lo} image ----------------
// layout: row n (output col), word w (k pair): uint2 at n*68 + w
__global__ void k_prepW(const float* __restrict__ W1, const float* __restrict__ W2,
                        const float* __restrict__ W3) {
    const float* Ws[3] = {W1, W2, W3};
    int l = blockIdx.x;
    const float* W = Ws[l];
    uint2* d = (uint2*)(g_Wiv + l * 4352);
#pragma unroll
    for (int it = 0; it < 32; it++) {
        int idx = it * 256 + threadIdx.x;      // 8192 = (n, w)
        int n = idx >> 6, w = idx & 63;
        float2 f = make_float2(W[(2 * w) * 128 + n], W[(2 * w + 1) * 128 + n]);
        uint32_t hi, lo;
        split_f2(f, hi, lo);
        d[n * 68 + w] = make_uint2(hi, lo);
    }
}

// ---------------- scans (dinv fused into part; goff fused into mid) ------------
#define SCAN_CHUNK 1024
#define SCAN_PARTS ((NN + SCAN_CHUNK - 1) / SCAN_CHUNK)

__global__ void k_scan_part() {
    __shared__ int s[256];
    int base = blockIdx.x * SCAN_CHUNK;
    int t = threadIdx.x;
    int sum = 0;
#pragma unroll
    for (int j = 0; j < 4; j++) {
        int i = base + t + j * 256;
        if (i < NN) {
            int d = g_deg[i];
            sum += d;
            g_dinv[i] = rsqrtf((float)d);
        }
    }
    s[t] = sum; __syncthreads();
    for (int off = 128; off; off >>= 1) {
        if (t < off) s[t] += s[t + off];
        __syncthreads();
    }
    if (t == 0) g_part[blockIdx.x] = s[0];
}

__global__ void k_scan_mid() {
    int run = 0;
#pragma unroll
    for (int p = 0; p < SCAN_PARTS; p++) {
        int v = g_part[p];
        g_part[p] = run;
        run += v;
    }
    g_rowoff[NN] = run;
    int g = 0;
#pragma unroll
    for (int q = 0; q < GG; q++) {
        g_goff[q] = g;
        g += g_gcnt[q];
    }
    g_goff[GG] = g;
}

__global__ void k_scan_final() {
    __shared__ int s[SCAN_CHUNK];
    int t = threadIdx.x;
    int i = blockIdx.x * SCAN_CHUNK + t;
    int v = (i < NN) ? g_deg[i] : 0;
    s[t] = v; __syncthreads();
    for (int off = 1; off < SCAN_CHUNK; off <<= 1) {
        int x = (t >= off) ? s[t - off] : 0;
        __syncthreads();
        s[t] += x;
        __syncthreads();
    }
    if (i < NN) g_rowoff[i] = g_part[blockIdx.x] + s[t] - v;
}

__global__ void k_fill(const int* __restrict__ ei) {
    int idx = blockIdx.x * blockDim.x + threadIdx.x;
    if (idx >= NEDGE) return;
    int s, d;
    if (idx < EE) { s = ei[idx]; d = ei[EE + idx]; }
    else          { s = d = idx - EE; }
    int pos = g_rowoff[d] + atomicAdd(&g_cursor[d], 1);
    float w = g_dinv[s] * g_dinv[d];
    g_cw[pos] = make_int2(s, __float_as_int(w));
}

// ---------------- tensor-core GEMM (mma.sync bf16x3): g_half = fp16(A @ W) -----
// block = 128x128 tile, 256 threads / 8 warps, warp = 16 rows x 128 cols.
// A fragments loaded directly from global (fp32) and split in registers;
// B staged in smem as interleaved {hi,lo} words -> one LDS.64 per fragment pair.
#define GSM 69632   // 128 rows * 68 uint2 * 8 B

#define MMA_BF16(C, A0, A1, A2, A3, B0, B1) \
    asm volatile("mma.sync.aligned.m16n8k16.row.col.f32.bf16.bf16.f32 " \
                 "{%0,%1,%2,%3}, {%4,%5,%6,%7}, {%8,%9}, {%0,%1,%2,%3};" \
                 : "+f"((C)[0]), "+f"((C)[1]), "+f"((C)[2]), "+f"((C)[3]) \
                 : "r"(A0), "r"(A1), "r"(A2), "r"(A3), "r"(B0), "r"(B1))

__global__ void __launch_bounds__(256, 2) k_gemm_mma(const float* __restrict__ Ain,
                                                     int layer) {
    extern __shared__ char smem[];
    const float* A = (layer == 0) ? Ain : g_bufB;
    int tid = threadIdx.x;
    int row0 = blockIdx.x << 7;

    // stage interleaved B image: 4352 uint4 = 68 KB
    {
        const uint4* src = g_Wiv + layer * 4352;
        uint4* dst = (uint4*)smem;
#pragma unroll
        for (int it = 0; it < 17; it++) {
            int i = it * 256 + tid;
            dst[i] = __ldg(&src[i]);
        }
    }
    __syncthreads();

    const uint2* pB = (const uint2*)smem;

    int lane = tid & 31, warp = tid >> 5;
    int rq = lane >> 2;        // 0..7
    int q = lane & 3;          // 0..3
    int arow = row0 + warp * 16 + rq;
    int arow8 = arow + 8;
    bool ok1 = arow < NN, ok2 = arow8 < NN;
    const float* a0p = A + (size_t)(ok1 ? arow : 0) * 128 + q * 2;
    const float* a1p = A + (size_t)(ok2 ? arow8 : 0) * 128 + q * 2;

    float c[16][4];
#pragma unroll
    for (int t = 0; t < 16; t++)
#pragma unroll
        for (int j = 0; j < 4; j++) c[t][j] = 0.f;

#pragma unroll
    for (int kk = 0; kk < 8; kk++) {
        int co = kk * 16;
        float2 f0 = ok1 ? *(const float2*)(a0p + co)     : make_float2(0.f, 0.f);
        float2 f1 = ok2 ? *(const float2*)(a1p + co)     : make_float2(0.f, 0.f);
        float2 f2 = ok1 ? *(const float2*)(a0p + co + 8) : make_float2(0.f, 0.f);
        float2 f3 = ok2 ? *(const float2*)(a1p + co + 8) : make_float2(0.f, 0.f);
        uint32_t ah0, al0, ah1, al1, ah2, al2, ah3, al3;
        split_f2(f0, ah0, al0);
        split_f2(f1, ah1, al1);
        split_f2(f2, ah2, al2);
        split_f2(f3, ah3, al3);
#pragma unroll
        for (int t = 0; t < 16; t++) {
            int bb = (t * 8 + rq) * 68 + kk * 8 + q;
            uint2 v0 = pB[bb];       // {bhi0, blo0}
            uint2 v1 = pB[bb + 4];   // {bhi1, blo1}
            MMA_BF16(c[t], ah0, ah1, ah2, ah3, v0.x, v1.x);
            MMA_BF16(c[t], al0, al1, al2, al3, v0.x, v1.x);
            MMA_BF16(c[t], ah0, ah1, ah2, ah3, v0.y, v1.y);
        }
    }

    // epilogue: fp16 stores straight from fragments
    unsigned short* gh = (unsigned short*)g_half;
#pragma unroll
    for (int t = 0; t < 16; t++) {
        int col = t * 8 + q * 2;
        if (ok1) {
            __half2 h = __floats2half2_rn(c[t][0], c[t][1]);
            *(unsigned*)(gh + (size_t)arow * 128 + col) = *(unsigned*)&h;
        }
        if (ok2) {
            __half2 h = __floats2half2_rn(c[t][2], c[t][3]);
            *(unsigned*)(gh + (size_t)arow8 * 128 + col) = *(unsigned*)&h;
        }
    }
}

// ---------------- CSR aggregation from fp16 features ----------------------------
__global__ void k_agg_h(const float* __restrict__ bias, int doRelu) {
    int warp = (blockIdx.x * blockDim.x + threadIdx.x) >> 5;
    int lane = threadIdx.x & 31;
    if (warp >= NN) return;
    int beg = g_rowoff[warp];
    int end = g_rowoff[warp + 1];
    const uint2* T = (const uint2*)g_half;
    float4 acc0 = make_float4(0.f, 0.f, 0.f, 0.f);
    float4 acc1 = make_float4(0.f, 0.f, 0.f, 0.f);
    int e = beg;
    for (; e + 3 < end; e += 4) {
        int2 cw0 = g_cw[e],     cw1 = g_cw[e + 1];
        int2 cw2 = g_cw[e + 2], cw3 = g_cw[e + 3];
        uint2 u0 = __ldg(&T[(size_t)cw0.x * 32 + lane]);
        uint2 u1 = __ldg(&T[(size_t)cw1.x * 32 + lane]);
        uint2 u2 = __ldg(&T[(size_t)cw2.x * 32 + lane]);
        uint2 u3 = __ldg(&T[(size_t)cw3.x * 32 + lane]);
        float w0 = __int_as_float(cw0.y), w1 = __int_as_float(cw1.y);
        float w2 = __int_as_float(cw2.y), w3 = __int_as_float(cw3.y);
        float2 a0 = __half22float2(*(__half2*)&u0.x), b0 = __half22float2(*(__half2*)&u0.y);
        float2 a1 = __half22float2(*(__half2*)&u1.x), b1 = __half22float2(*(__half2*)&u1.y);
        float2 a2 = __half22float2(*(__half2*)&u2.x), b2 = __half22float2(*(__half2*)&u2.y);
        float2 a3 = __half22float2(*(__half2*)&u3.x), b3 = __half22float2(*(__half2*)&u3.y);
        acc0.x = fmaf(w0, a0.x, acc0.x); acc0.y = fmaf(w0, a0.y, acc0.y);
        acc0.z = fmaf(w0, b0.x, acc0.z); acc0.w = fmaf(w0, b0.y, acc0.w);
        acc1.x = fmaf(w1, a1.x, acc1.x); acc1.y = fmaf(w1, a1.y, acc1.y);
        acc1.z = fmaf(w1, b1.x, acc1.z); acc1.w = fmaf(w1, b1.y, acc1.w);
        acc0.x = fmaf(w2, a2.x, acc0.x); acc0.y = fmaf(w2, a2.y, acc0.y);
        acc0.z = fmaf(w2, b2.x, acc0.z); acc0.w = fmaf(w2, b2.y, acc0.w);
        acc1.x = fmaf(w3, a3.x, acc1.x); acc1.y = fmaf(w3, a3.y, acc1.y);
        acc1.z = fmaf(w3, b3.x, acc1.z); acc1.w = fmaf(w3, b3.y, acc1.w);
    }
    for (; e < end; e++) {
        int2 cw = g_cw[e];
        float w = __int_as_float(cw.y);
        uint2 u = __ldg(&T[(size_t)cw.x * 32 + lane]);
        float2 a = __half22float2(*(__half2*)&u.x);
        float2 b = __half22float2(*(__half2*)&u.y);
        acc0.x = fmaf(w, a.x, acc0.x); acc0.y = fmaf(w, a.y, acc0.y);
        acc0.z = fmaf(w, b.x, acc0.z); acc0.w = fmaf(w, b.y, acc0.w);
    }
    float4 b4 = ((const float4*)bias)[lane];
    float4 r;
    r.x = acc0.x + acc1.x + b4.x;
    r.y = acc0.y + acc1.y + b4.y;
    r.z = acc0.z + acc1.z + b4.z;
    r.w = acc0.w + acc1.w + b4.w;
    if (doRelu) {
        r.x = fmaxf(r.x, 0.f); r.y = fmaxf(r.y, 0.f);
        r.z = fmaxf(r.z, 0.f); r.w = fmaxf(r.w, 0.f);
    }
    ((float4*)g_bufB)[(size_t)warp * 32 + lane] = r;
}

// ---------------- pooling --------------------------------------------------------
__global__ void k_pool() {
    int g = blockIdx.x >> 3;
    int s = blockIdx.x & 7;
    int col = threadIdx.x;
    int start = g_goff[g];
    int cnt = g_goff[g + 1] - start;
    int chunk = (cnt + 7) >> 3;
    int lo = start + s * chunk;
    int hi = lo + chunk;
    int ge = start + cnt;
    if (hi > ge) hi = ge;
    float sum = 0.f;
    int i = lo;
    for (; i + 3 < hi; i += 4) {
        sum += g_bufB[(size_t)(i + 0) * 128 + col];
        sum += g_bufB[(size_t)(i + 1) * 128 + col];
        sum += g_bufB[(size_t)(i + 2) * 128 + col];
        sum += g_bufB[(size_t)(i + 3) * 128 + col];
    }
    for (; i < hi; i++) sum += g_bufB[(size_t)i * 128 + col];
    if (lo < hi) atomicAdd(&g_pool[g * 128 + col], sum);
}

// ---------------- MLP head --------------------------------------------------------
__global__ void k_mlp(const float* __restrict__ Wo1, const float* __restrict__ bo1,
                      const float* __restrict__ Wo2, const float* __restrict__ bo2,
                      float* __restrict__ out) {
    __shared__ float ps[128];
    __shared__ float zs[64];
    int g = blockIdx.x;
    int t = threadIdx.x;
    float inv = 1.0f / fmaxf((float)g_gcnt[g], 1.0f);
    ps[t]      = g_pool[g * 128 + t] * inv;
    ps[t + 64] = g_pool[g * 128 + t + 64] * inv;
    __syncthreads();
    float z = bo1[t];
#pragma unroll 8
    for (int k = 0; k < 128; k++) z = fmaf(ps[k], Wo1[k * 64 + t], z);
    zs[t] = fmaxf(z, 0.f);
    __syncthreads();
    if (t < OUTD) {
        float o = bo2[t];
#pragma unroll 8
        for (int j = 0; j < 64; j++) o = fmaf(zs[j], Wo2[j * 32 + t], o);
        out[g * OUTD + t] = o;
    }
}

// ---------------- launch ------------------------------------------------------------
extern "C" void kernel_launch(void* const* d_in, const int* in_sizes, int n_in,
                              void* d_out, int out_size) {
    const float* x    = (const float*)d_in[0];
    const int*   ei   = (const int*)d_in[1];
    const int*   batch= (const int*)d_in[2];
    const float* W1   = (const float*)d_in[3];
    const float* b1   = (const float*)d_in[4];
    const float* W2   = (const float*)d_in[5];
    const float* b2   = (const float*)d_in[6];
    const float* W3   = (const float*)d_in[7];
    const float* b3   = (const float*)d_in[8];
    const float* Wo1  = (const float*)d_in[9];
    const float* bo1  = (const float*)d_in[10];
    const float* Wo2  = (const float*)d_in[11];
    const float* bo2  = (const float*)d_in[12];
    float* out = (float*)d_out;

    cudaFuncSetAttribute(k_gemm_mma, cudaFuncAttributeMaxDynamicSharedMemorySize, GSM);

    const int GEMM_BLOCKS = (NN + 127) / 128;
    const int AGG_BLOCKS  = (NN + 7) / 8;

    k_init<<<(NN + 255) / 256, 256>>>();                 // 0
    k_count<<<(EE + 255) / 256, 256>>>(ei, batch);       // 1
    k_prepW<<<3, 256>>>(W1, W2, W3);                     // 2
    k_gemm_mma<<<GEMM_BLOCKS, 256, GSM>>>(x, 0);         // 3  <- ncu slot
    k_scan_part<<<SCAN_PARTS, 256>>>();                  // 4
    k_scan_mid<<<1, 1>>>();                              // 5
    k_scan_final<<<SCAN_PARTS, SCAN_CHUNK>>>();          // 6
    k_fill<<<(NEDGE + 255) / 256, 256>>>(ei);            // 7

    k_agg_h<<<AGG_BLOCKS, 256>>>(b1, 1);                 // 8
    k_gemm_mma<<<GEMM_BLOCKS, 256, GSM>>>(x, 1);         // 9
    k_agg_h<<<AGG_BLOCKS, 256>>>(b2, 1);                 // 10
    k_gemm_mma<<<GEMM_BLOCKS, 256, GSM>>>(x, 2);         // 11
    k_agg_h<<<AGG_BLOCKS, 256>>>(b3, 0);                 // 12

    k_pool<<<GG * 8, 128>>>();                           // 13
    k_mlp<<<GG, 64>>>(Wo1, bo1, Wo2, bo2, out);          // 14
}